// round 8
// baseline (speedup 1.0000x reference)
#include <cuda_runtime.h>
#include <math.h>
#include <stdint.h>

#define BATCH 8192

// ---------------- scratch (static device globals; no allocation) ----------------
__device__ float g_pad [BATCH * 640];      // reflect-padded audio
__device__ float g_mag [32768 * 129];      // [b*4+t][f]
__device__ float g_e1  [32768 * 128];      // [b*4+t][c]
__device__ float g_e2  [16384 * 64];       // [b*2+t2][c]
__device__ float g_e3  [BATCH * 64];       // [b][c]
__device__ float g_Ag  [BATCH * 256];      // [b][ x(128) | h(128) ]
__device__ float g_gt  [BATCH * 512];      // gate pre-activations
// packed weights, K-major [K][N]
__device__ float g_Bstft[256 * 320];       // col 2f=real_f, 2f+1=imag_f, pad->0
__device__ float g_B1   [400 * 128];       // [tap*129+c][o], pad rows 387..399 = 0
__device__ float g_B2   [384 * 64];        // [tap*128+c][o]
__device__ float g_B3   [128 * 64];        // [(tap-1)*64+c][o], taps 1,2
__device__ float g_B4   [ 64 * 128];       // [c][o], center tap
__device__ float g_Bg   [256 * 512];       // [k][mat*128+o]

__device__ __forceinline__ float rna(float x) {
    asm("cvt.rna.tf32.f32 %0, %1;" : "=f"(x) : "f"(x));
    return x;
}

// ================= one fused prep kernel: pad + all weight packs + h copy =================
__global__ void k_prepW(const float* __restrict__ audio, const float* __restrict__ basis,
                        const float* __restrict__ w1, const float* __restrict__ w2,
                        const float* __restrict__ w3, const float* __restrict__ w4,
                        const float* __restrict__ wi, const float* __restrict__ wf,
                        const float* __restrict__ wg, const float* __restrict__ wo,
                        const float* __restrict__ ui, const float* __restrict__ uf,
                        const float* __restrict__ ug, const float* __restrict__ uo,
                        const float* __restrict__ h) {
    int i = blockIdx.x * 256 + threadIdx.x;
    if (i < 5242880) {                                     // reflect pad: 8192*640
        int b = i / 640, n = i - b * 640;
        int src = (n < 576) ? n : (1150 - n);
        g_pad[i] = audio[b * 576 + src];
        return;
    }
    i -= 5242880;
    if (i < 81920) {                                       // Bstft 256*320
        int k = i / 320, j = i - k * 320;
        float v = 0.f;
        if (j < 258) { int f = j >> 1, im = j & 1; v = basis[(im ? 129 + f : f) * 256 + k]; }
        g_Bstft[i] = v;
        return;
    }
    i -= 81920;
    if (i < 51200) {                                       // B1 400*128
        int kk = i >> 7, o = i & 127;
        float v = 0.f;
        if (kk < 387) { int kt = kk / 129, c = kk - kt * 129; v = w1[o * 387 + c * 3 + kt]; }
        g_B1[i] = v;
        return;
    }
    i -= 51200;
    if (i < 24576) {                                       // B2 384*64
        int kk = i >> 6, o = i & 63;
        int kt = kk >> 7, c = kk & 127;
        g_B2[i] = w2[o * 384 + c * 3 + kt];
        return;
    }
    i -= 24576;
    if (i < 8192) {                                        // B3 128*64
        int kk = i >> 6, o = i & 63;
        int kt = 1 + (kk >> 6), c = kk & 63;
        g_B3[i] = w3[o * 192 + c * 3 + kt];
        return;
    }
    i -= 8192;
    if (i < 8192) {                                        // B4 64*128
        int c = i >> 7, o = i & 127;
        g_B4[i] = w4[o * 192 + c * 3 + 1];
        return;
    }
    i -= 8192;
    if (i < 131072) {                                      // Bg 256*512
        int k = i >> 9, n = i & 511;
        int mat = n >> 7, o = n & 127;
        const float* W = (mat == 0) ? wi : (mat == 1) ? wf : (mat == 2) ? wg : wo;
        const float* U = (mat == 0) ? ui : (mat == 1) ? uf : (mat == 2) ? ug : uo;
        g_Bg[i] = (k < 128) ? W[o * 128 + k] : U[o * 128 + (k - 128)];
        return;
    }
    i -= 131072;
    if (i < 1048576) {                                     // h -> g_Ag[:,128:256]
        int b = i >> 7, o = i & 127;
        g_Ag[b * 256 + 128 + o] = h[b * 128 + o];
    }
}
// total elements = 6,596,608 = 25768 * 256

// ================= 3xTF32 tensor-core GEMM with fused im2col A-loader =================
// CTA tile 128x64, BK=16, 8 warps (4M x 2N), warp tile 32x32, mma m16n8k8.
// A row for layer L is a contiguous window [lo,hi) at start(row) of the source.
__device__ __forceinline__ void mma_tf32(float (&d)[4], const uint32_t (&a)[4], const uint32_t (&b)[2]) {
    asm volatile("mma.sync.aligned.m16n8k8.row.col.f32.tf32.tf32.f32 "
                 "{%0,%1,%2,%3}, {%4,%5,%6,%7}, {%8,%9}, {%0,%1,%2,%3};"
                 : "+f"(d[0]), "+f"(d[1]), "+f"(d[2]), "+f"(d[3])
                 : "r"(a[0]), "r"(a[1]), "r"(a[2]), "r"(a[3]), "r"(b[0]), "r"(b[1]));
}

// smem layout (floats): AH[2][16][136] @0 (4352), AL @4352, BH[2][16][72] @8704 (2304), BL @11008
#define SMEM_FLOATS 13312
#define SMEM_BYTES  (SMEM_FLOATS * 4)

template <int L>
__global__ __launch_bounds__(256) void k_gemm3(const float* __restrict__ A,
                                               const float* __restrict__ B,
                                               float* __restrict__ C,
                                               const float* __restrict__ bias) {
    constexpr int K   = (L == 0) ? 256 : (L == 1) ? 400 : (L == 2) ? 384 : (L == 3) ? 128 : (L == 4) ? 64 : 256;
    constexpr int NP  = (L == 0) ? 320 : (L == 1) ? 128 : (L == 2) ? 64  : (L == 3) ? 64  : (L == 4) ? 128 : 512;
    constexpr int LDC = (L == 0) ? 129 : (L == 1) ? 128 : (L == 2) ? 64  : (L == 3) ? 64  : (L == 4) ? 256 : 512;
    constexpr bool RELU = (L >= 1 && L <= 4);

    extern __shared__ float sm[];
    float* AH = sm;
    float* AL = sm + 4352;
    float* BH = sm + 8704;
    float* BL = sm + 11008;

    const int m0 = blockIdx.x * 128, n0 = blockIdx.y * 64;
    const int tid = threadIdx.x, lane = tid & 31, warp = tid >> 5;
    const int wm = warp >> 1, wn = warp & 1, r = lane >> 2, q = lane & 3;
    const int am = tid >> 1, akq = (tid & 1) * 8;   // A loader: row am, 8 k's
    const int bk = tid >> 4, bn = (tid & 15) * 4;   // B loader: k-row bk, 4 n's

    // per-thread im2col window for row m0+am
    const int row = m0 + am;
    long start;
    int lo, hi;
    if (L == 0)      { int b = row >> 2, t = row & 3; start = (long)b * 640 + t * 128; lo = 0; hi = K; }
    else if (L == 1) { int t = row & 3; start = (long)(row - 1) * 129; lo = (t == 0) ? 129 : 0; hi = (t == 3) ? 258 : 387; }
    else if (L == 2) { int t2 = row & 1, b = row >> 1; start = (long)(b * 4 + 2 * t2 - 1) * 128; lo = (t2 == 0) ? 128 : 0; hi = 384; }
    else if (L == 3) { start = (long)row * 128; lo = 0; hi = K; }
    else if (L == 4) { start = (long)row * 64;  lo = 0; hi = K; }
    else             { start = (long)row * 256; lo = 0; hi = K; }

    const float* Bbase = B + bk * NP + n0 + bn;

    float pa[8];
    float4 pb;
#pragma unroll
    for (int j = 0; j < 8; j++) {
        int gk = akq + j;
        pa[j] = (gk >= lo && gk < hi) ? __ldg(A + start + gk) : 0.f;
    }
    pb = *(const float4*)(Bbase);

    float acc[2][4][4] = {};
    int buf = 0;
    // stage tile 0
    {
#pragma unroll
        for (int j = 0; j < 8; j++) {
            float x = pa[j], hx = rna(x);
            AH[(akq + j) * 136 + am] = hx;
            AL[(akq + j) * 136 + am] = rna(x - hx);
        }
        float bv[4] = {pb.x, pb.y, pb.z, pb.w};
#pragma unroll
        for (int j = 0; j < 4; j++) {
            float x = bv[j], hx = rna(x);
            BH[bk * 72 + bn + j] = hx;
            BL[bk * 72 + bn + j] = rna(x - hx);
        }
    }
    __syncthreads();

#pragma unroll 1
    for (int k0 = 0; k0 < K; k0 += 16) {
        const bool has = (k0 + 16) < K;
        if (has) {
#pragma unroll
            for (int j = 0; j < 8; j++) {
                int gk = k0 + 16 + akq + j;
                pa[j] = (gk >= lo && gk < hi) ? __ldg(A + start + gk) : 0.f;
            }
            pb = *(const float4*)(Bbase + (long)(k0 + 16) * NP);
        }
#pragma unroll
        for (int kq = 0; kq < 16; kq += 8) {
            uint32_t ah[2][4], al[2][4], bh[4][2], bl[4][2];
#pragma unroll
            for (int mi = 0; mi < 2; mi++) {
                int mb = wm * 32 + mi * 16 + r;
                int i0 = buf * 2176 + (kq + q) * 136;
                int i1 = buf * 2176 + (kq + q + 4) * 136;
                ah[mi][0] = __float_as_uint(AH[i0 + mb]);     al[mi][0] = __float_as_uint(AL[i0 + mb]);
                ah[mi][1] = __float_as_uint(AH[i0 + mb + 8]); al[mi][1] = __float_as_uint(AL[i0 + mb + 8]);
                ah[mi][2] = __float_as_uint(AH[i1 + mb]);     al[mi][2] = __float_as_uint(AL[i1 + mb]);
                ah[mi][3] = __float_as_uint(AH[i1 + mb + 8]); al[mi][3] = __float_as_uint(AL[i1 + mb + 8]);
            }
#pragma unroll
            for (int ni = 0; ni < 4; ni++) {
                int nb = wn * 32 + ni * 8 + r;
                int i0 = buf * 1152 + (kq + q) * 72;
                int i1 = buf * 1152 + (kq + q + 4) * 72;
                bh[ni][0] = __float_as_uint(BH[i0 + nb]); bl[ni][0] = __float_as_uint(BL[i0 + nb]);
                bh[ni][1] = __float_as_uint(BH[i1 + nb]); bl[ni][1] = __float_as_uint(BL[i1 + nb]);
            }
#pragma unroll
            for (int mi = 0; mi < 2; mi++)
#pragma unroll
                for (int ni = 0; ni < 4; ni++) {
                    mma_tf32(acc[mi][ni], ah[mi], bh[ni]);
                    mma_tf32(acc[mi][ni], al[mi], bh[ni]);
                    mma_tf32(acc[mi][ni], ah[mi], bl[ni]);
                }
        }
        if (has) {
            int ob = buf ^ 1;
#pragma unroll
            for (int j = 0; j < 8; j++) {
                float x = pa[j], hx = rna(x);
                AH[ob * 2176 + (akq + j) * 136 + am] = hx;
                AL[ob * 2176 + (akq + j) * 136 + am] = rna(x - hx);
            }
            float bv[4] = {pb.x, pb.y, pb.z, pb.w};
#pragma unroll
            for (int j = 0; j < 4; j++) {
                float x = bv[j], hx = rna(x);
                BH[ob * 1152 + bk * 72 + bn + j] = hx;
                BL[ob * 1152 + bk * 72 + bn + j] = rna(x - hx);
            }
        }
        __syncthreads();
        buf ^= 1;
    }

    // epilogue
#pragma unroll
    for (int mi = 0; mi < 2; mi++) {
        int orow = m0 + wm * 32 + mi * 16 + r;
#pragma unroll
        for (int ni = 0; ni < 4; ni++) {
            int col = n0 + wn * 32 + ni * 8 + q * 2;
            float c0 = acc[mi][ni][0], c1 = acc[mi][ni][1];
            float c2 = acc[mi][ni][2], c3 = acc[mi][ni][3];
            if (L == 0) {
                int f = col >> 1;
                if (f < 129) {
                    C[(long)orow * 129 + f]       = sqrtf(c0 * c0 + c1 * c1);
                    C[(long)(orow + 8) * 129 + f] = sqrtf(c2 * c2 + c3 * c3);
                }
            } else {
                float b0 = 0.f, b1 = 0.f;
                if (bias) { b0 = __ldg(bias + col); b1 = __ldg(bias + col + 1); }
                float v0 = c0 + b0, v1 = c1 + b1, v2 = c2 + b0, v3 = c3 + b1;
                if (RELU) {
                    v0 = fmaxf(v0, 0.f); v1 = fmaxf(v1, 0.f);
                    v2 = fmaxf(v2, 0.f); v3 = fmaxf(v3, 0.f);
                }
                *(float2*)&C[(long)orow * LDC + col]       = make_float2(v0, v1);
                *(float2*)&C[(long)(orow + 8) * LDC + col] = make_float2(v2, v3);
            }
        }
    }
}

// ================= final: LSTM cell + head =================
__global__ __launch_bounds__(128) void k_final(const float* __restrict__ cin,
    const float* __restrict__ bxi, const float* __restrict__ bxf,
    const float* __restrict__ bxg, const float* __restrict__ bxo,
    const float* __restrict__ bhi, const float* __restrict__ bhf,
    const float* __restrict__ bhg, const float* __restrict__ bho,
    const float* __restrict__ cw, const float* __restrict__ cb,
    float* __restrict__ out, int writeHC) {
    const int b = blockIdx.x, o = threadIdx.x;
    const float* g = g_gt + b * 512;
    float pi = g[o]       + __ldg(bxi + o) + __ldg(bhi + o);
    float pf = g[128 + o] + __ldg(bxf + o) + __ldg(bhf + o);
    float pg = g[256 + o] + __ldg(bxg + o) + __ldg(bhg + o);
    float po = g[384 + o] + __ldg(bxo + o) + __ldg(bho + o);
    float ig = 1.f / (1.f + expf(-pi));
    float fg = 1.f / (1.f + expf(-pf));
    float gg = tanhf(pg);
    float og = 1.f / (1.f + expf(-po));
    float co = fg * cin[b * 128 + o] + ig * gg;
    float ho = og * tanhf(co);
    if (writeHC) {
        out[BATCH + b * 128 + o] = ho;
        out[BATCH + BATCH * 128 + b * 128 + o] = co;
    }
    __shared__ float red[128];
    float y = ho > 0.f ? ho : 0.f;
    red[o] = y * __ldg(cw + o);
    __syncthreads();
    for (int s = 64; s > 0; s >>= 1) {
        if (o < s) red[o] += red[o + s];
        __syncthreads();
    }
    if (o == 0) out[b] = 1.f / (1.f + expf(-(red[0] + cb[0])));
}

// ================= launch =================
extern "C" void kernel_launch(void* const* d_in, const int* in_sizes, int n_in,
                              void* d_out, int out_size) {
    const float* audio = (const float*)d_in[0];
    const float* h     = (const float*)d_in[1];
    const float* cin   = (const float*)d_in[2];
    const float* basis = (const float*)d_in[3];
    const float* w1 = (const float*)d_in[4];  const float* b1 = (const float*)d_in[5];
    const float* w2 = (const float*)d_in[6];  const float* b2 = (const float*)d_in[7];
    const float* w3 = (const float*)d_in[8];  const float* b3 = (const float*)d_in[9];
    const float* w4 = (const float*)d_in[10]; const float* b4 = (const float*)d_in[11];
    const float* wi = (const float*)d_in[12]; const float* wf = (const float*)d_in[13];
    const float* wg = (const float*)d_in[14]; const float* wo = (const float*)d_in[15];
    const float* ui = (const float*)d_in[16]; const float* uf = (const float*)d_in[17];
    const float* ug = (const float*)d_in[18]; const float* uo = (const float*)d_in[19];
    const float* bxi = (const float*)d_in[20]; const float* bxf = (const float*)d_in[21];
    const float* bxg = (const float*)d_in[22]; const float* bxo = (const float*)d_in[23];
    const float* bhi = (const float*)d_in[24]; const float* bhf = (const float*)d_in[25];
    const float* bhg = (const float*)d_in[26]; const float* bho = (const float*)d_in[27];
    const float* cw  = (const float*)d_in[28]; const float* cb  = (const float*)d_in[29];
    float* out = (float*)d_out;
    int writeHC = (out_size >= BATCH * 257) ? 1 : 0;

    float *pPad, *pMag, *pE1, *pE2, *pE3, *pAg, *pGt;
    float *pBstft, *pB1, *pB2, *pB3, *pB4, *pBg;
    cudaGetSymbolAddress((void**)&pPad, g_pad);
    cudaGetSymbolAddress((void**)&pMag, g_mag);
    cudaGetSymbolAddress((void**)&pE1, g_e1);
    cudaGetSymbolAddress((void**)&pE2, g_e2);
    cudaGetSymbolAddress((void**)&pE3, g_e3);
    cudaGetSymbolAddress((void**)&pAg, g_Ag);
    cudaGetSymbolAddress((void**)&pGt, g_gt);
    cudaGetSymbolAddress((void**)&pBstft, g_Bstft);
    cudaGetSymbolAddress((void**)&pB1, g_B1);
    cudaGetSymbolAddress((void**)&pB2, g_B2);
    cudaGetSymbolAddress((void**)&pB3, g_B3);
    cudaGetSymbolAddress((void**)&pB4, g_B4);
    cudaGetSymbolAddress((void**)&pBg, g_Bg);

    cudaFuncSetAttribute(k_gemm3<0>, cudaFuncAttributeMaxDynamicSharedMemorySize, SMEM_BYTES);
    cudaFuncSetAttribute(k_gemm3<1>, cudaFuncAttributeMaxDynamicSharedMemorySize, SMEM_BYTES);
    cudaFuncSetAttribute(k_gemm3<2>, cudaFuncAttributeMaxDynamicSharedMemorySize, SMEM_BYTES);
    cudaFuncSetAttribute(k_gemm3<3>, cudaFuncAttributeMaxDynamicSharedMemorySize, SMEM_BYTES);
    cudaFuncSetAttribute(k_gemm3<4>, cudaFuncAttributeMaxDynamicSharedMemorySize, SMEM_BYTES);
    cudaFuncSetAttribute(k_gemm3<5>, cudaFuncAttributeMaxDynamicSharedMemorySize, SMEM_BYTES);

    // prep: reflect pad + all weight packs + h copy (one kernel)
    k_prepW<<<25768, 256>>>(audio, basis, w1, w2, w3, w4,
                            wi, wf, wg, wo, ui, uf, ug, uo, h);
    // STFT + magnitude
    { dim3 gr(256, 5); k_gemm3<0><<<gr, 256, SMEM_BYTES>>>(pPad, pBstft, pMag, nullptr); }
    // enc1
    { dim3 gr(256, 2); k_gemm3<1><<<gr, 256, SMEM_BYTES>>>(pMag, pB1, pE1, b1); }
    // enc2
    { dim3 gr(128, 1); k_gemm3<2><<<gr, 256, SMEM_BYTES>>>(pE1, pB2, pE2, b2); }
    // enc3
    { dim3 gr(64, 1);  k_gemm3<3><<<gr, 256, SMEM_BYTES>>>(pE2, pB3, pE3, b3); }
    // enc4 -> x into g_Ag[:,0:128]
    { dim3 gr(64, 2);  k_gemm3<4><<<gr, 256, SMEM_BYTES>>>(pE3, pB4, pAg, b4); }
    // gates
    { dim3 gr(64, 8);  k_gemm3<5><<<gr, 256, SMEM_BYTES>>>(pAg, pBg, pGt, nullptr); }
    // LSTM cell + head
    k_final<<<BATCH, 128>>>(cin, bxi, bxf, bxg, bxo, bhi, bhf, bhg, bho, cw, cb, out, writeHC);
}

// round 11
// speedup vs baseline: 1.3795x; 1.3795x over previous
#include <cuda_runtime.h>
#include <cuda_bf16.h>
#include <math.h>
#include <stdint.h>

#define BATCH 8192

// ---------------- scratch (static device globals; no allocation) ----------------
__device__ float g_mag [32768 * 129];      // [b*4+t][f]
__device__ float g_e1  [32768 * 128];      // [b*4+t][c]
__device__ float g_e2  [16384 * 64];       // [b*2+t2][c]
__device__ float g_e3  [BATCH * 64];       // [b][c]
__device__ float g_x   [BATCH * 128];      // enc4 out = LSTM input
__device__ float g_gt  [BATCH * 512];      // gate pre-activations
// packed weights, K-major [K][N]
__device__ float g_Bstft[256 * 320];       // col 2f=real_f, 2f+1=imag_f, pad->0
__device__ float g_B1   [400 * 128];       // [tap*129+c][o], rows 387..399 = 0
__device__ float g_B2   [384 * 64];        // [tap*128+c][o]
__device__ float g_B3   [128 * 64];        // [(tap-1)*64+c][o], taps 1,2
__device__ float g_B4   [ 64 * 128];       // [c][o], center tap only
__device__ float g_Bg   [256 * 512];       // [k][mat*128+o]

__device__ __forceinline__ float bfr(float x) {         // round to bf16, back to f32
    return __bfloat162float(__float2bfloat16_rn(x));
}
__device__ __forceinline__ uint32_t bfpack(float e, float o) {  // lo16=e (even k), hi16=o (odd k)
    uint32_t r;
    asm("cvt.rn.bf16x2.f32 %0, %1, %2;" : "=r"(r) : "f"(o), "f"(e));
    return r;
}

// ================= prep: weight packing only =================
__global__ void k_prepW(const float* __restrict__ basis,
                        const float* __restrict__ w1, const float* __restrict__ w2,
                        const float* __restrict__ w3, const float* __restrict__ w4,
                        const float* __restrict__ wi, const float* __restrict__ wf,
                        const float* __restrict__ wg, const float* __restrict__ wo,
                        const float* __restrict__ ui, const float* __restrict__ uf,
                        const float* __restrict__ ug, const float* __restrict__ uo) {
    int i = blockIdx.x * 256 + threadIdx.x;
    if (i < 81920) {                                       // Bstft 256*320
        int k = i / 320, j = i - k * 320;
        float v = 0.f;
        if (j < 258) { int f = j >> 1, im = j & 1; v = basis[(im ? 129 + f : f) * 256 + k]; }
        g_Bstft[i] = v;
        return;
    }
    i -= 81920;
    if (i < 51200) {                                       // B1 400*128
        int kk = i >> 7, o = i & 127;
        float v = 0.f;
        if (kk < 387) { int kt = kk / 129, c = kk - kt * 129; v = w1[o * 387 + c * 3 + kt]; }
        g_B1[i] = v;
        return;
    }
    i -= 51200;
    if (i < 24576) {                                       // B2 384*64
        int kk = i >> 6, o = i & 63;
        int kt = kk >> 7, c = kk & 127;
        g_B2[i] = w2[o * 384 + c * 3 + kt];
        return;
    }
    i -= 24576;
    if (i < 8192) {                                        // B3 128*64
        int kk = i >> 6, o = i & 63;
        int kt = 1 + (kk >> 6), c = kk & 63;
        g_B3[i] = w3[o * 192 + c * 3 + kt];
        return;
    }
    i -= 8192;
    if (i < 8192) {                                        // B4 64*128
        int c = i >> 7, o = i & 127;
        g_B4[i] = w4[o * 192 + c * 3 + 1];
        return;
    }
    i -= 8192;
    if (i < 131072) {                                      // Bg 256*512
        int k = i >> 9, n = i & 511;
        int mat = n >> 7, o = n & 127;
        const float* W = (mat == 0) ? wi : (mat == 1) ? wf : (mat == 2) ? wg : wo;
        const float* U = (mat == 0) ? ui : (mat == 1) ? uf : (mat == 2) ? ug : uo;
        g_Bg[i] = (k < 128) ? W[o * 128 + k] : U[o * 128 + (k - 128)];
    }
}
// total = 305152 elems -> 1192 blocks of 256

// ================= split-bf16 (3-term) tensor-core GEMM, fused im2col loader =================
// CTA tile 128x64, BK=16 (one m16n8k16 slab), 8 warps (4M x 2N), warp tile 32x32.
__device__ __forceinline__ void mma_bf16(float (&d)[4], const uint32_t (&a)[4], const uint32_t (&b)[2]) {
    asm volatile("mma.sync.aligned.m16n8k16.row.col.f32.bf16.bf16.f32 "
                 "{%0,%1,%2,%3}, {%4,%5,%6,%7}, {%8,%9}, {%0,%1,%2,%3};"
                 : "+f"(d[0]), "+f"(d[1]), "+f"(d[2]), "+f"(d[3])
                 : "r"(a[0]), "r"(a[1]), "r"(a[2]), "r"(a[3]), "r"(b[0]), "r"(b[1]));
}

template <int L>
__global__ __launch_bounds__(256) void k_gemm(const float* __restrict__ A,
                                              const float* __restrict__ A2,
                                              const float* __restrict__ B,
                                              float* __restrict__ C,
                                              const float* __restrict__ bias) {
    constexpr int K   = (L == 0) ? 256 : (L == 1) ? 400 : (L == 2) ? 384 : (L == 3) ? 128 : (L == 4) ? 64 : 256;
    constexpr int NP  = (L == 0) ? 320 : (L == 1) ? 128 : (L == 2) ? 64  : (L == 3) ? 64  : (L == 4) ? 128 : 512;
    constexpr int LDC = (L == 0) ? 129 : (L == 1) ? 128 : (L == 2) ? 64  : (L == 3) ? 64  : (L == 4) ? 128 : 512;
    constexpr bool RELU = (L >= 1 && L <= 4);

    // packed bf16x2 smem: [buf][k2 (8)][stride]
    __shared__ uint32_t AH[2 * 8 * 136], AL[2 * 8 * 136];
    __shared__ uint32_t BH[2 * 8 * 72],  BL[2 * 8 * 72];

    const int m0 = blockIdx.x * 128, n0 = blockIdx.y * 64;
    const int tid = threadIdx.x, lane = tid & 31, warp = tid >> 5;
    const int wm = warp >> 1, wn = warp & 1, r = lane >> 2, q = lane & 3;
    // A loader: row am, 8 consecutive k starting at akq
    const int am = tid >> 1, akq = (tid & 1) * 8, k2b = (tid & 1) * 4;
    // B loader: k-pair row k2r, 2 consecutive n at nn
    const int k2r = tid >> 5, nn = (lane) * 2;

    // per-thread im2col window for A row (m0+am)
    const int row = m0 + am;
    const float* Abase = A;   // L0: audio row base
    const float* Ax = A;      // L5
    const float* Ah = A2;     // L5
    long start = 0; int lo = 0, hi = K, t128 = 0;
    if (L == 0)      { Abase = A + (long)(row >> 2) * 576; t128 = (row & 3) * 128; }
    else if (L == 1) { int t = row & 3; start = (long)(row - 1) * 129; lo = (t == 0) ? 129 : 0; hi = (t == 3) ? 258 : 387; }
    else if (L == 2) { int t2 = row & 1, b = row >> 1; start = (long)(b * 4 + 2 * t2 - 1) * 128; lo = (t2 == 0) ? 128 : 0; hi = 384; }
    else if (L == 3) { start = (long)row * 128; }
    else if (L == 4) { start = (long)row * 64; }
    else             { Ax = A + (long)row * 128; Ah = A2 + (long)row * 128; }

    const float* Bbase = B + k2r * 2 * NP + n0 + nn;

    float pa[8];
    float pb00, pb01, pb10, pb11;
    auto fetchA = [&](int gk) -> float {
        if (L == 0) {
            int s = t128 + gk;
            int src = (s < 576) ? s : (1150 - s);
            return __ldg(Abase + src);
        } else if (L == 5) {
            return (gk < 128) ? __ldg(Ax + gk) : __ldg(Ah + gk - 128);
        } else {
            return (gk >= lo && gk < hi) ? __ldg(A + start + gk) : 0.f;
        }
    };
    auto fetchB = [&](int k0) {
        float2 v0 = *(const float2*)(Bbase + (long)k0 * NP);
        float2 v1 = *(const float2*)(Bbase + (long)k0 * NP + NP);
        pb00 = v0.x; pb01 = v0.y; pb10 = v1.x; pb11 = v1.y;
    };
    auto stage = [&](int buf) {
        int ab = buf * 1088, bb = buf * 576;
#pragma unroll
        for (int jj = 0; jj < 4; jj++) {
            float x0 = pa[2 * jj], x1 = pa[2 * jj + 1];
            float h0 = bfr(x0), h1 = bfr(x1);
            AH[ab + (k2b + jj) * 136 + am] = bfpack(h0, h1);
            AL[ab + (k2b + jj) * 136 + am] = bfpack(x0 - h0, x1 - h1);
        }
        float h00 = bfr(pb00), h01 = bfr(pb01), h10 = bfr(pb10), h11 = bfr(pb11);
        uint2 hv = make_uint2(bfpack(h00, h10), bfpack(h01, h11));
        uint2 lv = make_uint2(bfpack(pb00 - h00, pb10 - h10), bfpack(pb01 - h01, pb11 - h11));
        *(uint2*)&BH[bb + k2r * 72 + nn] = hv;
        *(uint2*)&BL[bb + k2r * 72 + nn] = lv;
    };

#pragma unroll
    for (int j = 0; j < 8; j++) pa[j] = fetchA(akq + j);
    fetchB(0);

    float acc[2][4][4] = {};
    int buf = 0;
    stage(0);
    __syncthreads();

#pragma unroll 1
    for (int k0 = 0; k0 < K; k0 += 16) {
        const bool has = (k0 + 16) < K;
        if (has) {
#pragma unroll
            for (int j = 0; j < 8; j++) pa[j] = fetchA(k0 + 16 + akq + j);
            fetchB(k0 + 16);
        }
        // fragments
        uint32_t ah[2][4], al[2][4], bh[4][2], bl[4][2];
        {
            int ab = buf * 1088, bb = buf * 576;
            int i0 = ab + q * 136, i1 = ab + (q + 4) * 136;
#pragma unroll
            for (int mi = 0; mi < 2; mi++) {
                int mb = wm * 32 + mi * 16 + r;
                ah[mi][0] = AH[i0 + mb];     al[mi][0] = AL[i0 + mb];
                ah[mi][1] = AH[i0 + mb + 8]; al[mi][1] = AL[i0 + mb + 8];
                ah[mi][2] = AH[i1 + mb];     al[mi][2] = AL[i1 + mb];
                ah[mi][3] = AH[i1 + mb + 8]; al[mi][3] = AL[i1 + mb + 8];
            }
            int j0 = bb + q * 72, j1 = bb + (q + 4) * 72;
#pragma unroll
            for (int ni = 0; ni < 4; ni++) {
                int nb = wn * 32 + ni * 8 + r;
                bh[ni][0] = BH[j0 + nb]; bl[ni][0] = BL[j0 + nb];
                bh[ni][1] = BH[j1 + nb]; bl[ni][1] = BL[j1 + nb];
            }
        }
#pragma unroll
        for (int mi = 0; mi < 2; mi++)
#pragma unroll
            for (int ni = 0; ni < 4; ni++) {
                mma_bf16(acc[mi][ni], ah[mi], bh[ni]);
                mma_bf16(acc[mi][ni], al[mi], bh[ni]);
                mma_bf16(acc[mi][ni], ah[mi], bl[ni]);
            }
        if (has) stage(buf ^ 1);
        __syncthreads();
        buf ^= 1;
    }

    // epilogue
#pragma unroll
    for (int mi = 0; mi < 2; mi++) {
        int orow = m0 + wm * 32 + mi * 16 + r;
#pragma unroll
        for (int ni = 0; ni < 4; ni++) {
            int col = n0 + wn * 32 + ni * 8 + q * 2;
            float c0 = acc[mi][ni][0], c1 = acc[mi][ni][1];
            float c2 = acc[mi][ni][2], c3 = acc[mi][ni][3];
            if (L == 0) {
                int f = col >> 1;
                if (f < 129) {
                    C[(long)orow * 129 + f]       = sqrtf(c0 * c0 + c1 * c1);
                    C[(long)(orow + 8) * 129 + f] = sqrtf(c2 * c2 + c3 * c3);
                }
            } else {
                float b0 = 0.f, b1 = 0.f;
                if (bias) { b0 = __ldg(bias + col); b1 = __ldg(bias + col + 1); }
                float v0 = c0 + b0, v1 = c1 + b1, v2 = c2 + b0, v3 = c3 + b1;
                if (RELU) {
                    v0 = fmaxf(v0, 0.f); v1 = fmaxf(v1, 0.f);
                    v2 = fmaxf(v2, 0.f); v3 = fmaxf(v3, 0.f);
                }
                *(float2*)&C[(long)orow * LDC + col]       = make_float2(v0, v1);
                *(float2*)&C[(long)(orow + 8) * LDC + col] = make_float2(v2, v3);
            }
        }
    }
}

// ================= final: LSTM cell + head =================
__global__ __launch_bounds__(128) void k_final(const float* __restrict__ cin,
    const float* __restrict__ bxi, const float* __restrict__ bxf,
    const float* __restrict__ bxg, const float* __restrict__ bxo,
    const float* __restrict__ bhi, const float* __restrict__ bhf,
    const float* __restrict__ bhg, const float* __restrict__ bho,
    const float* __restrict__ cw, const float* __restrict__ cb,
    float* __restrict__ out, int writeHC) {
    const int b = blockIdx.x, o = threadIdx.x;
    const float* g = g_gt + b * 512;
    float pi = g[o]       + __ldg(bxi + o) + __ldg(bhi + o);
    float pf = g[128 + o] + __ldg(bxf + o) + __ldg(bhf + o);
    float pg = g[256 + o] + __ldg(bxg + o) + __ldg(bhg + o);
    float po = g[384 + o] + __ldg(bxo + o) + __ldg(bho + o);
    float ig = 1.f / (1.f + expf(-pi));
    float fg = 1.f / (1.f + expf(-pf));
    float gg = tanhf(pg);
    float og = 1.f / (1.f + expf(-po));
    float co = fg * cin[b * 128 + o] + ig * gg;
    float ho = og * tanhf(co);
    if (writeHC) {
        out[BATCH + b * 128 + o] = ho;
        out[BATCH + BATCH * 128 + b * 128 + o] = co;
    }
    __shared__ float red[128];
    float y = ho > 0.f ? ho : 0.f;
    red[o] = y * __ldg(cw + o);
    __syncthreads();
    for (int s = 64; s > 0; s >>= 1) {
        if (o < s) red[o] += red[o + s];
        __syncthreads();
    }
    if (o == 0) out[b] = 1.f / (1.f + expf(-(red[0] + cb[0])));
}

// ================= launch =================
extern "C" void kernel_launch(void* const* d_in, const int* in_sizes, int n_in,
                              void* d_out, int out_size) {
    const float* audio = (const float*)d_in[0];
    const float* h     = (const float*)d_in[1];
    const float* cin   = (const float*)d_in[2];
    const float* basis = (const float*)d_in[3];
    const float* w1 = (const float*)d_in[4];  const float* b1 = (const float*)d_in[5];
    const float* w2 = (const float*)d_in[6];  const float* b2 = (const float*)d_in[7];
    const float* w3 = (const float*)d_in[8];  const float* b3 = (const float*)d_in[9];
    const float* w4 = (const float*)d_in[10]; const float* b4 = (const float*)d_in[11];
    const float* wi = (const float*)d_in[12]; const float* wf = (const float*)d_in[13];
    const float* wg = (const float*)d_in[14]; const float* wo = (const float*)d_in[15];
    const float* ui = (const float*)d_in[16]; const float* uf = (const float*)d_in[17];
    const float* ug = (const float*)d_in[18]; const float* uo = (const float*)d_in[19];
    const float* bxi = (const float*)d_in[20]; const float* bxf = (const float*)d_in[21];
    const float* bxg = (const float*)d_in[22]; const float* bxo = (const float*)d_in[23];
    const float* bhi = (const float*)d_in[24]; const float* bhf = (const float*)d_in[25];
    const float* bhg = (const float*)d_in[26]; const float* bho = (const float*)d_in[27];
    const float* cw  = (const float*)d_in[28]; const float* cb  = (const float*)d_in[29];
    float* out = (float*)d_out;
    int writeHC = (out_size >= BATCH * 257) ? 1 : 0;

    float *pMag, *pE1, *pE2, *pE3, *pX, *pGt;
    float *pBstft, *pB1, *pB2, *pB3, *pB4, *pBg;
    cudaGetSymbolAddress((void**)&pMag, g_mag);
    cudaGetSymbolAddress((void**)&pE1, g_e1);
    cudaGetSymbolAddress((void**)&pE2, g_e2);
    cudaGetSymbolAddress((void**)&pE3, g_e3);
    cudaGetSymbolAddress((void**)&pX,  g_x);
    cudaGetSymbolAddress((void**)&pGt, g_gt);
    cudaGetSymbolAddress((void**)&pBstft, g_Bstft);
    cudaGetSymbolAddress((void**)&pB1, g_B1);
    cudaGetSymbolAddress((void**)&pB2, g_B2);
    cudaGetSymbolAddress((void**)&pB3, g_B3);
    cudaGetSymbolAddress((void**)&pB4, g_B4);
    cudaGetSymbolAddress((void**)&pBg, g_Bg);

    // weight packing
    k_prepW<<<1192, 256>>>(basis, w1, w2, w3, w4, wi, wf, wg, wo, ui, uf, ug, uo);
    // STFT + magnitude (reflect pad fused in loader)
    { dim3 gr(256, 5); k_gemm<0><<<gr, 256>>>(audio, nullptr, pBstft, pMag, nullptr); }
    // enc1
    { dim3 gr(256, 2); k_gemm<1><<<gr, 256>>>(pMag, nullptr, pB1, pE1, b1); }
    // enc2
    { dim3 gr(128, 1); k_gemm<2><<<gr, 256>>>(pE1, nullptr, pB2, pE2, b2); }
    // enc3
    { dim3 gr(64, 1);  k_gemm<3><<<gr, 256>>>(pE2, nullptr, pB3, pE3, b3); }
    // enc4 -> x
    { dim3 gr(64, 2);  k_gemm<4><<<gr, 256>>>(pE3, nullptr, pB4, pX, b4); }
    // gates ([x|h] read from two sources in loader)
    { dim3 gr(64, 8);  k_gemm<5><<<gr, 256>>>(pX, h, pBg, pGt, nullptr); }
    // LSTM cell + head
    k_final<<<BATCH, 128>>>(cin, bxi, bxf, bxg, bxo, bhi, bhf, bhg, bho, cw, cb, out, writeHC);
}

// round 15
// speedup vs baseline: 1.3917x; 1.0089x over previous
#include <cuda_runtime.h>
#include <cuda_bf16.h>
#include <math.h>
#include <stdint.h>

#define BATCH 8192

// ---------------- scratch (static device globals; no allocation) ----------------
__device__ float g_mag [32768 * 129];      // [b*4+t][f]
__device__ float g_e1  [32768 * 128];      // [b*4+t][c]
__device__ float g_e2  [16384 * 64];       // [b*2+t2][c]
__device__ float g_e3  [BATCH * 64];       // [b][c]
__device__ float g_x   [BATCH * 128];      // enc4 out = LSTM input
__device__ float g_dotp[BATCH * 16];       // head dot partials [b][ctaY*2+wn]
// packed weights, K-major [K][N]
__device__ float g_Bstft[256 * 320];       // col 2f=real_f, 2f+1=imag_f, pad->0
__device__ float g_B1   [400 * 128];       // [tap*129+c][o], rows 387..399 = 0
__device__ float g_B2   [384 * 64];        // [tap*128+c][o]
__device__ float g_B3   [128 * 64];        // [(tap-1)*64+c][o], taps 1,2
__device__ float g_B4   [ 64 * 128];       // [c][o], center tap only
__device__ float g_Bg   [256 * 512];       // [k][o*4+mat]  (interleaved gates)
__device__ float g_bias [512];             // [o*4+mat] = bx+bh

__device__ __forceinline__ float bfr(float x) {
    return __bfloat162float(__float2bfloat16_rn(x));
}
__device__ __forceinline__ uint32_t bfpack(float e, float o) {  // lo16=e, hi16=o
    uint32_t r;
    asm("cvt.rn.bf16x2.f32 %0, %1, %2;" : "=r"(r) : "f"(o), "f"(e));
    return r;
}

// ================= prep: weight packing =================
__global__ void k_prepW(const float* __restrict__ basis,
                        const float* __restrict__ w1, const float* __restrict__ w2,
                        const float* __restrict__ w3, const float* __restrict__ w4,
                        const float* __restrict__ wi, const float* __restrict__ wf,
                        const float* __restrict__ wg, const float* __restrict__ wo,
                        const float* __restrict__ ui, const float* __restrict__ uf,
                        const float* __restrict__ ug, const float* __restrict__ uo,
                        const float* __restrict__ bxi, const float* __restrict__ bxf,
                        const float* __restrict__ bxg, const float* __restrict__ bxo,
                        const float* __restrict__ bhi, const float* __restrict__ bhf,
                        const float* __restrict__ bhg, const float* __restrict__ bho) {
    int i = blockIdx.x * 256 + threadIdx.x;
    if (i < 81920) {                                       // Bstft 256*320
        int k = i / 320, j = i - k * 320;
        float v = 0.f;
        if (j < 258) { int f = j >> 1, im = j & 1; v = basis[(im ? 129 + f : f) * 256 + k]; }
        g_Bstft[i] = v;
        return;
    }
    i -= 81920;
    if (i < 51200) {                                       // B1 400*128
        int kk = i >> 7, o = i & 127;
        float v = 0.f;
        if (kk < 387) { int kt = kk / 129, c = kk - kt * 129; v = w1[o * 387 + c * 3 + kt]; }
        g_B1[i] = v;
        return;
    }
    i -= 51200;
    if (i < 24576) {                                       // B2 384*64
        int kk = i >> 6, o = i & 63;
        int kt = kk >> 7, c = kk & 127;
        g_B2[i] = w2[o * 384 + c * 3 + kt];
        return;
    }
    i -= 24576;
    if (i < 8192) {                                        // B3 128*64
        int kk = i >> 6, o = i & 63;
        int kt = 1 + (kk >> 6), c = kk & 63;
        g_B3[i] = w3[o * 192 + c * 3 + kt];
        return;
    }
    i -= 8192;
    if (i < 8192) {                                        // B4 64*128
        int c = i >> 7, o = i & 127;
        g_B4[i] = w4[o * 192 + c * 3 + 1];
        return;
    }
    i -= 8192;
    if (i < 131072) {                                      // Bg 256*512 interleaved col=o*4+mat
        int k = i >> 9, n = i & 511;
        int o = n >> 2, mat = n & 3;
        const float* W = (mat == 0) ? wi : (mat == 1) ? wf : (mat == 2) ? wg : wo;
        const float* U = (mat == 0) ? ui : (mat == 1) ? uf : (mat == 2) ? ug : uo;
        g_Bg[i] = (k < 128) ? W[o * 128 + k] : U[o * 128 + (k - 128)];
        return;
    }
    i -= 131072;
    if (i < 512) {                                         // bias interleaved
        int o = i >> 2, mat = i & 3;
        const float* bx = (mat == 0) ? bxi : (mat == 1) ? bxf : (mat == 2) ? bxg : bxo;
        const float* bh = (mat == 0) ? bhi : (mat == 1) ? bhf : (mat == 2) ? bhg : bho;
        g_bias[i] = bx[o] + bh[o];
    }
}
// total = 305664 elems -> 1194 blocks of 256

// ================= split-bf16 (3-term) tensor-core GEMM, fused im2col loader =================
// TM=128: 8 warps (4Mx2N); TM=64: 4 warps (2Mx2N). Warp tile 32x32, mma m16n8k16, BK=16.
__device__ __forceinline__ void mma_bf16(float (&d)[4], const uint32_t (&a)[4], const uint32_t (&b)[2]) {
    asm volatile("mma.sync.aligned.m16n8k16.row.col.f32.bf16.bf16.f32 "
                 "{%0,%1,%2,%3}, {%4,%5,%6,%7}, {%8,%9}, {%0,%1,%2,%3};"
                 : "+f"(d[0]), "+f"(d[1]), "+f"(d[2]), "+f"(d[3])
                 : "r"(a[0]), "r"(a[1]), "r"(a[2]), "r"(a[3]), "r"(b[0]), "r"(b[1]));
}

__device__ __forceinline__ float sigf(float x) { return 1.f / (1.f + expf(-x)); }

template <int L>
__global__ __launch_bounds__((L == 0 || L == 1 || L == 5) ? 256 : 128)
void k_gemm(const float* __restrict__ A, const float* __restrict__ A2,
            const float* __restrict__ B, float* __restrict__ C,
            const float* __restrict__ bias,
            const float* __restrict__ cin, const float* __restrict__ cw,
            float* __restrict__ out, int writeHC) {
    constexpr int K   = (L == 0) ? 256 : (L == 1) ? 400 : (L == 2) ? 384 : (L == 3) ? 128 : (L == 4) ? 64 : 256;
    constexpr int NP  = (L == 0) ? 320 : (L == 1) ? 128 : (L == 2) ? 64  : (L == 3) ? 64  : (L == 4) ? 128 : 512;
    constexpr int LDC = (L == 0) ? 129 : (L == 1) ? 128 : (L == 2) ? 64  : (L == 3) ? 64  : (L == 4) ? 128 : 512;
    constexpr bool RELU = (L >= 1 && L <= 4);
    constexpr int TM   = (L == 0 || L == 1 || L == 5) ? 128 : 64;
    constexpr int ASTR = TM + 8;
    constexpr int KPT  = (TM == 128) ? 1 : 2;   // B-loader k-pair rows per thread

    __shared__ uint32_t AH[2 * 8 * ASTR], AL[2 * 8 * ASTR];
    __shared__ uint32_t BH[2 * 8 * 72],  BL[2 * 8 * 72];

    const int m0 = blockIdx.x * TM, n0 = blockIdx.y * 64;
    const int tid = threadIdx.x, lane = tid & 31, warp = tid >> 5;
    const int wm = warp >> 1, wn = warp & 1, r = lane >> 2, q = lane & 3;
    const int am = tid >> 1, akq = (tid & 1) * 8, k2b = (tid & 1) * 4;
    const int k2r = tid >> 5, nn = lane * 2;

    // per-thread im2col window for A row (m0+am)
    const int row = m0 + am;
    const float* Abase = A;
    const float* Ax = A;
    const float* Ah = A2;
    long start = 0; int lo = 0, hi = K, t128 = 0;
    if (L == 0)      { Abase = A + (long)(row >> 2) * 576; t128 = (row & 3) * 128; }
    else if (L == 1) { int t = row & 3; start = (long)(row - 1) * 129; lo = (t == 0) ? 129 : 0; hi = (t == 3) ? 258 : 387; }
    else if (L == 2) { int t2 = row & 1, b = row >> 1; start = (long)(b * 4 + 2 * t2 - 1) * 128; lo = (t2 == 0) ? 128 : 0; hi = 384; }
    else if (L == 3) { start = (long)row * 128; }
    else if (L == 4) { start = (long)row * 64; }
    else             { Ax = A + (long)row * 128; Ah = A2 + (long)row * 128; }

    float pa[8];
    float pb[KPT][4];
    auto fetchA = [&](int gk) -> float {
        if (L == 0) {
            int s = t128 + gk;
            int src = (s < 576) ? s : (1150 - s);
            return __ldg(Abase + src);
        } else if (L == 5) {
            return (gk < 128) ? __ldg(Ax + gk) : __ldg(Ah + gk - 128);
        } else {
            return (gk >= lo && gk < hi) ? __ldg(A + start + gk) : 0.f;
        }
    };
    auto fetchB = [&](int k0) {
#pragma unroll
        for (int kp = 0; kp < KPT; kp++) {
            const float* bp = B + (long)(k0 + (k2r + kp * 4) * 2) * NP + n0 + nn;
            float2 v0 = *(const float2*)bp;
            float2 v1 = *(const float2*)(bp + NP);
            pb[kp][0] = v0.x; pb[kp][1] = v0.y; pb[kp][2] = v1.x; pb[kp][3] = v1.y;
        }
    };
    auto stage = [&](int buf) {
        int ab = buf * (8 * ASTR), bb = buf * 576;
#pragma unroll
        for (int jj = 0; jj < 4; jj++) {
            float x0 = pa[2 * jj], x1 = pa[2 * jj + 1];
            float h0 = bfr(x0), h1 = bfr(x1);
            AH[ab + (k2b + jj) * ASTR + am] = bfpack(h0, h1);
            AL[ab + (k2b + jj) * ASTR + am] = bfpack(x0 - h0, x1 - h1);
        }
#pragma unroll
        for (int kp = 0; kp < KPT; kp++) {
            float h00 = bfr(pb[kp][0]), h01 = bfr(pb[kp][1]);
            float h10 = bfr(pb[kp][2]), h11 = bfr(pb[kp][3]);
            uint2 hv = make_uint2(bfpack(h00, h10), bfpack(h01, h11));
            uint2 lv = make_uint2(bfpack(pb[kp][0] - h00, pb[kp][2] - h10),
                                  bfpack(pb[kp][1] - h01, pb[kp][3] - h11));
            *(uint2*)&BH[bb + (k2r + kp * 4) * 72 + nn] = hv;
            *(uint2*)&BL[bb + (k2r + kp * 4) * 72 + nn] = lv;
        }
    };

#pragma unroll
    for (int j = 0; j < 8; j++) pa[j] = fetchA(akq + j);
    fetchB(0);

    float acc[2][4][4] = {};
    int buf = 0;
    stage(0);
    __syncthreads();

#pragma unroll 1
    for (int k0 = 0; k0 < K; k0 += 16) {
        const bool has = (k0 + 16) < K;
        if (has) {
#pragma unroll
            for (int j = 0; j < 8; j++) pa[j] = fetchA(k0 + 16 + akq + j);
            fetchB(k0 + 16);
        }
        uint32_t ah[2][4], al[2][4], bh[4][2], bl[4][2];
        {
            int ab = buf * (8 * ASTR), bb = buf * 576;
            int i0 = ab + q * ASTR, i1 = ab + (q + 4) * ASTR;
#pragma unroll
            for (int mi = 0; mi < 2; mi++) {
                int mb = wm * 32 + mi * 16 + r;
                ah[mi][0] = AH[i0 + mb];     al[mi][0] = AL[i0 + mb];
                ah[mi][1] = AH[i0 + mb + 8]; al[mi][1] = AL[i0 + mb + 8];
                ah[mi][2] = AH[i1 + mb];     al[mi][2] = AL[i1 + mb];
                ah[mi][3] = AH[i1 + mb + 8]; al[mi][3] = AL[i1 + mb + 8];
            }
            int j0 = bb + q * 72, j1 = bb + (q + 4) * 72;
#pragma unroll
            for (int ni = 0; ni < 4; ni++) {
                int nb = wn * 32 + ni * 8 + r;
                bh[ni][0] = BH[j0 + nb]; bl[ni][0] = BL[j0 + nb];
                bh[ni][1] = BH[j1 + nb]; bl[ni][1] = BL[j1 + nb];
            }
        }
#pragma unroll
        for (int mi = 0; mi < 2; mi++)
#pragma unroll
            for (int ni = 0; ni < 4; ni++) {
                mma_bf16(acc[mi][ni], ah[mi], bh[ni]);
                mma_bf16(acc[mi][ni], al[mi], bh[ni]);
                mma_bf16(acc[mi][ni], ah[mi], bl[ni]);
            }
        if (has) stage(buf ^ 1);
        __syncthreads();
        buf ^= 1;
    }

    // ---------------- epilogue ----------------
    if (L == 5) {
        // interleaved gates -> LSTM cell fused; head partials to g_dotp
#pragma unroll
        for (int mi = 0; mi < 2; mi++) {
            int orow = m0 + wm * 32 + mi * 16 + r;
            float d0 = 0.f, d1 = 0.f;
#pragma unroll
            for (int ni = 0; ni < 4; ni++) {
                int col = n0 + wn * 32 + ni * 8 + q * 2;
                float b0 = __ldg(bias + col), b1 = __ldg(bias + col + 1);
                float v0 = acc[mi][ni][0] + b0, v1 = acc[mi][ni][1] + b1;
                float v2 = acc[mi][ni][2] + b0, v3 = acc[mi][ni][3] + b1;
                float u0 = __shfl_xor_sync(0xffffffff, v0, 1);
                float u1 = __shfl_xor_sync(0xffffffff, v1, 1);
                float u2 = __shfl_xor_sync(0xffffffff, v2, 1);
                float u3 = __shfl_xor_sync(0xffffffff, v3, 1);
                if (!(q & 1)) {   // this thread holds (i,f); partner holds (g,o)
                    int o = col >> 2;
                    float cwv = __ldg(cw + o);
                    {
                        float ig = sigf(v0), fg = sigf(v1), gg = tanhf(u0), og = sigf(u1);
                        float co = fg * __ldg(cin + (long)orow * 128 + o) + ig * gg;
                        float ho = og * tanhf(co);
                        if (writeHC) {
                            out[BATCH + orow * 128 + o] = ho;
                            out[BATCH + BATCH * 128 + orow * 128 + o] = co;
                        }
                        d0 += fmaxf(ho, 0.f) * cwv;
                    }
                    {
                        float ig = sigf(v2), fg = sigf(v3), gg = tanhf(u2), og = sigf(u3);
                        float co = fg * __ldg(cin + (long)(orow + 8) * 128 + o) + ig * gg;
                        float ho = og * tanhf(co);
                        if (writeHC) {
                            out[BATCH + (orow + 8) * 128 + o] = ho;
                            out[BATCH + BATCH * 128 + (orow + 8) * 128 + o] = co;
                        }
                        d1 += fmaxf(ho, 0.f) * cwv;
                    }
                }
            }
            d0 += __shfl_xor_sync(0xffffffff, d0, 2);
            d1 += __shfl_xor_sync(0xffffffff, d1, 2);
            if (q == 0) {
                g_dotp[orow * 16 + blockIdx.y * 2 + wn] = d0;
                g_dotp[(orow + 8) * 16 + blockIdx.y * 2 + wn] = d1;
            }
        }
    } else {
#pragma unroll
        for (int mi = 0; mi < 2; mi++) {
            int orow = m0 + wm * 32 + mi * 16 + r;
#pragma unroll
            for (int ni = 0; ni < 4; ni++) {
                int col = n0 + wn * 32 + ni * 8 + q * 2;
                float c0 = acc[mi][ni][0], c1 = acc[mi][ni][1];
                float c2 = acc[mi][ni][2], c3 = acc[mi][ni][3];
                if (L == 0) {
                    int f = col >> 1;
                    if (f < 129) {
                        C[(long)orow * 129 + f]       = sqrtf(c0 * c0 + c1 * c1);
                        C[(long)(orow + 8) * 129 + f] = sqrtf(c2 * c2 + c3 * c3);
                    }
                } else {
                    float b0 = __ldg(bias + col), b1 = __ldg(bias + col + 1);
                    float v0 = c0 + b0, v1 = c1 + b1, v2 = c2 + b0, v3 = c3 + b1;
                    if (RELU) {
                        v0 = fmaxf(v0, 0.f); v1 = fmaxf(v1, 0.f);
                        v2 = fmaxf(v2, 0.f); v3 = fmaxf(v3, 0.f);
                    }
                    *(float2*)&C[(long)orow * LDC + col]       = make_float2(v0, v1);
                    *(float2*)&C[(long)(orow + 8) * LDC + col] = make_float2(v2, v3);
                }
            }
        }
    }
}

// ================= prob head: sum 16 partials, sigmoid =================
__global__ __launch_bounds__(256) void k_prob(const float* __restrict__ cb,
                                              float* __restrict__ out) {
    int b = blockIdx.x * 256 + threadIdx.x;
    const float4* p = (const float4*)(g_dotp + b * 16);
    float4 a0 = p[0], a1 = p[1], a2 = p[2], a3 = p[3];
    float s = (a0.x + a0.y + a0.z + a0.w) + (a1.x + a1.y + a1.z + a1.w)
            + (a2.x + a2.y + a2.z + a2.w) + (a3.x + a3.y + a3.z + a3.w);
    out[b] = 1.f / (1.f + expf(-(s + cb[0])));
}

// ================= launch =================
extern "C" void kernel_launch(void* const* d_in, const int* in_sizes, int n_in,
                              void* d_out, int out_size) {
    const float* audio = (const float*)d_in[0];
    const float* h     = (const float*)d_in[1];
    const float* cin   = (const float*)d_in[2];
    const float* basis = (const float*)d_in[3];
    const float* w1 = (const float*)d_in[4];  const float* b1 = (const float*)d_in[5];
    const float* w2 = (const float*)d_in[6];  const float* b2 = (const float*)d_in[7];
    const float* w3 = (const float*)d_in[8];  const float* b3 = (const float*)d_in[9];
    const float* w4 = (const float*)d_in[10]; const float* b4 = (const float*)d_in[11];
    const float* wi = (const float*)d_in[12]; const float* wf = (const float*)d_in[13];
    const float* wg = (const float*)d_in[14]; const float* wo = (const float*)d_in[15];
    const float* ui = (const float*)d_in[16]; const float* uf = (const float*)d_in[17];
    const float* ug = (const float*)d_in[18]; const float* uo = (const float*)d_in[19];
    const float* bxi = (const float*)d_in[20]; const float* bxf = (const float*)d_in[21];
    const float* bxg = (const float*)d_in[22]; const float* bxo = (const float*)d_in[23];
    const float* bhi = (const float*)d_in[24]; const float* bhf = (const float*)d_in[25];
    const float* bhg = (const float*)d_in[26]; const float* bho = (const float*)d_in[27];
    const float* cw  = (const float*)d_in[28]; const float* cb  = (const float*)d_in[29];
    float* out = (float*)d_out;
    int writeHC = (out_size >= BATCH * 257) ? 1 : 0;

    float *pMag, *pE1, *pE2, *pE3, *pX;
    float *pBstft, *pB1, *pB2, *pB3, *pB4, *pBg, *pBias;
    cudaGetSymbolAddress((void**)&pMag, g_mag);
    cudaGetSymbolAddress((void**)&pE1, g_e1);
    cudaGetSymbolAddress((void**)&pE2, g_e2);
    cudaGetSymbolAddress((void**)&pE3, g_e3);
    cudaGetSymbolAddress((void**)&pX,  g_x);
    cudaGetSymbolAddress((void**)&pBstft, g_Bstft);
    cudaGetSymbolAddress((void**)&pB1, g_B1);
    cudaGetSymbolAddress((void**)&pB2, g_B2);
    cudaGetSymbolAddress((void**)&pB3, g_B3);
    cudaGetSymbolAddress((void**)&pB4, g_B4);
    cudaGetSymbolAddress((void**)&pBg, g_Bg);
    cudaGetSymbolAddress((void**)&pBias, g_bias);

    // weight packing (+ interleaved gate weights/bias)
    k_prepW<<<1194, 256>>>(basis, w1, w2, w3, w4, wi, wf, wg, wo, ui, uf, ug, uo,
                           bxi, bxf, bxg, bxo, bhi, bhf, bhg, bho);
    // STFT + magnitude (reflect pad fused in loader)
    { dim3 gr(256, 5); k_gemm<0><<<gr, 256>>>(audio, nullptr, pBstft, pMag, nullptr, nullptr, nullptr, nullptr, 0); }
    // enc1
    { dim3 gr(256, 2); k_gemm<1><<<gr, 256>>>(pMag, nullptr, pB1, pE1, b1, nullptr, nullptr, nullptr, 0); }
    // enc2 (64-row tiles, 4 warps)
    { dim3 gr(256, 1); k_gemm<2><<<gr, 128>>>(pE1, nullptr, pB2, pE2, b2, nullptr, nullptr, nullptr, 0); }
    // enc3
    { dim3 gr(128, 1); k_gemm<3><<<gr, 128>>>(pE2, nullptr, pB3, pE3, b3, nullptr, nullptr, nullptr, 0); }
    // enc4 -> x
    { dim3 gr(128, 2); k_gemm<4><<<gr, 128>>>(pE3, nullptr, pB4, pX, b4, nullptr, nullptr, nullptr, 0); }
    // gates + fused LSTM cell (h_out/c_out written directly; head partials to g_dotp)
    { dim3 gr(64, 8);  k_gemm<5><<<gr, 256>>>(pX, h, pBg, nullptr, pBias, cin, cw, out, writeHC); }
    // prob head
    k_prob<<<32, 256>>>(cb, out);
}